// round 1
// baseline (speedup 1.0000x reference)
#include <cuda_runtime.h>
#include <math.h>

#define N_SEQ 4096
#define SEQ_S 128
#define T_STEPS 127
#define VOCAB 36
#define E_DIM 128
#define H_DIM 256
#define G_DIM 1024            // 4*H
#define NH (N_SEQ * H_DIM)    // 1048576

static const size_t PROBS_OFF = (size_t)N_SEQ * T_STEPS * VOCAB;  // 18726912

// ---------------- scratch (device globals; no allocation allowed) ----------------
__device__ __align__(128) float g_h0[2][NH];                       // layer0 h ping-pong
__device__ __align__(128) float g_hz[NH];                          // zero h for t=0
__device__ __align__(128) float g_c0[NH];
__device__ __align__(128) float g_c1[NH];
__device__ __align__(128) float g_h1all[(size_t)T_STEPS * NH];     // layer1 h, all steps (533MB)
__device__ __align__(128) float g_Wcat0[G_DIM * 384];              // [W_ih0 | W_hh0], gate-permuted rows
__device__ __align__(128) float g_Wcat1[G_DIM * 512];              // [W_ih1 | W_hh1], gate-permuted rows
__device__ float g_bcat0[G_DIM];
__device__ float g_bcat1[G_DIM];
__device__ float g_acc[N_SEQ];                                     // masked NLL accumulator
__device__ float g_len[N_SEQ];

// ---------------- helpers ----------------
typedef unsigned long long ull;

__device__ __forceinline__ ull pack2(float x, float y) {
    ull r; asm("mov.b64 %0, {%1,%2};" : "=l"(r) : "f"(x), "f"(y)); return r;
}
__device__ __forceinline__ void unpack2(ull v, float& x, float& y) {
    asm("mov.b64 {%0,%1}, %2;" : "=f"(x), "=f"(y) : "l"(v));
}
// sm_103a packed fp32 FMA: d = a*b + d (per 32-bit lane)
__device__ __forceinline__ void ffma2(ull& d, ull a, ull b) {
    asm("fma.rn.f32x2 %0, %1, %2, %0;" : "+l"(d) : "l"(a), "l"(b));
}
__device__ __forceinline__ float sigmf(float v) { return 1.0f / (1.0f + expf(-v)); }

// ---------------- prep: permute gate rows into (i,f,g,o) quadruples, concat W_ih|W_hh ----------------
__global__ void prep_kernel(const float* __restrict__ W_ih0, const float* __restrict__ W_hh0,
                            const float* __restrict__ b_ih0, const float* __restrict__ b_hh0,
                            const float* __restrict__ W_ih1, const float* __restrict__ W_hh1,
                            const float* __restrict__ b_ih1, const float* __restrict__ b_hh1) {
    int jp = blockIdx.x;                 // permuted row 0..1023
    int gate = jp & 3, q = jp >> 2;
    int j = gate * H_DIM + q;            // original row
    int tid = threadIdx.x;               // 128 threads
    for (int k = tid; k < E_DIM; k += 128) g_Wcat0[jp * 384 + k] = W_ih0[j * E_DIM + k];
    for (int k = tid; k < H_DIM; k += 128) g_Wcat0[jp * 384 + E_DIM + k] = W_hh0[j * H_DIM + k];
    for (int k = tid; k < H_DIM; k += 128) g_Wcat1[jp * 512 + k] = W_ih1[j * H_DIM + k];
    for (int k = tid; k < H_DIM; k += 128) g_Wcat1[jp * 512 + H_DIM + k] = W_hh1[j * H_DIM + k];
    if (tid == 0) {
        g_bcat0[jp] = b_ih0[j] + b_hh0[j];
        g_bcat1[jp] = b_ih1[j] + b_hh1[j];
    }
}

// ---------------- init: zero state (re-done every launch; must be deterministic) ----------------
__global__ void init_kernel() {
    int i = blockIdx.x * blockDim.x + threadIdx.x;   // exactly NH threads
    g_hz[i] = 0.0f;
    g_c0[i] = 0.0f;
    g_c1[i] = 0.0f;
    if (i < N_SEQ) g_acc[i] = 0.0f;
}

// ---------------- lengths ----------------
__global__ void len_kernel(const int* __restrict__ x) {
    int n = blockIdx.x * 8 + (threadIdx.x >> 5);
    int lane = threadIdx.x & 31;
    int cnt = 0;
    for (int j = lane; j < SEQ_S; j += 32) cnt += (x[n * SEQ_S + j] != 0);
    for (int o = 16; o; o >>= 1) cnt += __shfl_down_sync(0xffffffffu, cnt, o);
    if (lane == 0) g_len[n] = (float)cnt;
}

// ---------------- fused LSTM step: gates GEMM (fp32x2 FFMA) + pointwise update ----------------
// Block tile: 128 sequences x 64 permuted gate cols (16 complete quadruples), K = KIN + 256.
// Thread (tx,ty): rows rowBase + ty*8 + {0..7}, cols colBase + tx*4 + {0..3} (one quadruple).
template <int KIN>
__global__ __launch_bounds__(256)
void lstm_step_kernel(const float* __restrict__ emb, const int* __restrict__ x, int t) {
    constexpr int KTOT = KIN + H_DIM;
    constexpr int NT = KTOT / 16;
    __shared__ float As[16][132];
    __shared__ float Bs[16][68];
    __shared__ int tokS[128];

    const float* inp; const float* hprev; float* hnew; float* cst;
    const float* Wc; const float* bc;
    if (KIN == E_DIM) {  // layer 0: input = embedding gather
        inp = emb;
        hprev = (t == 0) ? g_hz : g_h0[(t - 1) & 1];
        hnew = g_h0[t & 1];
        cst = g_c0; Wc = g_Wcat0; bc = g_bcat0;
    } else {             // layer 1: input = layer0 output of this step
        inp = g_h0[t & 1];
        hprev = (t == 0) ? g_hz : (g_h1all + (size_t)(t - 1) * NH);
        hnew = g_h1all + (size_t)t * NH;
        cst = g_c1; Wc = g_Wcat1; bc = g_bcat1;
    }

    const int rowBase = blockIdx.y * 128;
    const int colBase = blockIdx.x * 64;
    const int tid = threadIdx.x;
    const int tx = tid & 15, ty = tid >> 4;

    if (tid < 128)
        tokS[tid] = (KIN == E_DIM) ? x[(rowBase + tid) * SEQ_S + t] : (rowBase + tid);
    __syncthreads();

    float4 aR0, aR1, bR;

    auto loadA = [&](int kt, int s) -> float4 {
        int row = s >> 2, k4 = s & 3;
        int gk = kt * 16 + k4 * 4;
        const float* p = (gk < KIN)
            ? (inp + (size_t)tokS[row] * KIN + gk)
            : (hprev + (size_t)(rowBase + row) * H_DIM + (gk - KIN));
        return *(const float4*)p;
    };
    auto loadB = [&](int kt) -> float4 {
        int c = tid >> 2, k4 = tid & 3;
        return *(const float4*)(Wc + (size_t)(colBase + c) * KTOT + kt * 16 + k4 * 4);
    };
    auto storeT = [&]() {
        int r0 = tid >> 2, k4 = tid & 3;
        As[k4 * 4 + 0][r0] = aR0.x; As[k4 * 4 + 1][r0] = aR0.y;
        As[k4 * 4 + 2][r0] = aR0.z; As[k4 * 4 + 3][r0] = aR0.w;
        int r1 = r0 + 64;
        As[k4 * 4 + 0][r1] = aR1.x; As[k4 * 4 + 1][r1] = aR1.y;
        As[k4 * 4 + 2][r1] = aR1.z; As[k4 * 4 + 3][r1] = aR1.w;
        int c = tid >> 2;
        Bs[k4 * 4 + 0][c] = bR.x; Bs[k4 * 4 + 1][c] = bR.y;
        Bs[k4 * 4 + 2][c] = bR.z; Bs[k4 * 4 + 3][c] = bR.w;
    };

    ull acc[4][4];
#pragma unroll
    for (int u = 0; u < 4; u++)
#pragma unroll
        for (int j = 0; j < 4; j++) acc[u][j] = pack2(0.0f, 0.0f);

    aR0 = loadA(0, tid); aR1 = loadA(0, tid + 256); bR = loadB(0);
    storeT();
    __syncthreads();

    for (int kt = 0; kt < NT; kt++) {
        if (kt + 1 < NT) {
            aR0 = loadA(kt + 1, tid); aR1 = loadA(kt + 1, tid + 256); bR = loadB(kt + 1);
        }
#pragma unroll
        for (int k = 0; k < 16; k++) {
            ull ap0 = *(const ull*)&As[k][ty * 8 + 0];
            ull ap1 = *(const ull*)&As[k][ty * 8 + 2];
            ull ap2 = *(const ull*)&As[k][ty * 8 + 4];
            ull ap3 = *(const ull*)&As[k][ty * 8 + 6];
            float4 b4 = *(const float4*)&Bs[k][tx * 4];
            ull bp0 = pack2(b4.x, b4.x), bp1 = pack2(b4.y, b4.y);
            ull bp2 = pack2(b4.z, b4.z), bp3 = pack2(b4.w, b4.w);
            ffma2(acc[0][0], ap0, bp0); ffma2(acc[0][1], ap0, bp1);
            ffma2(acc[0][2], ap0, bp2); ffma2(acc[0][3], ap0, bp3);
            ffma2(acc[1][0], ap1, bp0); ffma2(acc[1][1], ap1, bp1);
            ffma2(acc[1][2], ap1, bp2); ffma2(acc[1][3], ap1, bp3);
            ffma2(acc[2][0], ap2, bp0); ffma2(acc[2][1], ap2, bp1);
            ffma2(acc[2][2], ap2, bp2); ffma2(acc[2][3], ap2, bp3);
            ffma2(acc[3][0], ap3, bp0); ffma2(acc[3][1], ap3, bp1);
            ffma2(acc[3][2], ap3, bp2); ffma2(acc[3][3], ap3, bp3);
        }
        __syncthreads();
        if (kt + 1 < NT) { storeT(); __syncthreads(); }
    }

    // pointwise LSTM update (this thread owns quadruple q for its 8 rows)
    float bi = bc[colBase + tx * 4 + 0];
    float bf = bc[colBase + tx * 4 + 1];
    float bg = bc[colBase + tx * 4 + 2];
    float bo = bc[colBase + tx * 4 + 3];
    int q = (colBase >> 2) + tx;
#pragma unroll
    for (int u = 0; u < 4; u++) {
        float gi0, gi1, gf0, gf1, gg0, gg1, go0, go1;
        unpack2(acc[u][0], gi0, gi1);
        unpack2(acc[u][1], gf0, gf1);
        unpack2(acc[u][2], gg0, gg1);
        unpack2(acc[u][3], go0, go1);
        int r = rowBase + ty * 8 + 2 * u;
        {
            size_t ci = (size_t)r * H_DIM + q;
            float ii = sigmf(gi0 + bi), ff = sigmf(gf0 + bf);
            float gg = tanhf(gg0 + bg), oo = sigmf(go0 + bo);
            float cn = ff * cst[ci] + ii * gg;
            cst[ci] = cn;
            hnew[ci] = oo * tanhf(cn);
        }
        {
            size_t ci = (size_t)(r + 1) * H_DIM + q;
            float ii = sigmf(gi1 + bi), ff = sigmf(gf1 + bf);
            float gg = tanhf(gg1 + bg), oo = sigmf(go1 + bo);
            float cn = ff * cst[ci] + ii * gg;
            cst[ci] = cn;
            hnew[ci] = oo * tanhf(cn);
        }
    }
}

// ---------------- fc + relu + log_softmax + probs + masked NLL, for all (n,t) ----------------
// Block: 8 sequences x 36 vocab = 288 threads; grid (N/8, T)
__global__ __launch_bounds__(288)
void fc_kernel(const float* __restrict__ fc_W, const float* __restrict__ fc_b,
               const int* __restrict__ x, float* __restrict__ out) {
    __shared__ float Ws[VOCAB][H_DIM + 1];   // 36*257*4 = 37KB
    __shared__ float hs[8][H_DIM];           // 8KB
    __shared__ float lg[8][VOCAB + 2];
    __shared__ float lse_s[8];

    const int t = blockIdx.y;
    const int n0 = blockIdx.x * 8;
    const int tid = threadIdx.x;

    for (int i = tid; i < VOCAB * H_DIM; i += 288) Ws[i / H_DIM][i % H_DIM] = fc_W[i];
    const float* hsrc = g_h1all + (size_t)t * NH + (size_t)n0 * H_DIM;
    for (int i = tid; i < 8 * H_DIM; i += 288) hs[i / H_DIM][i % H_DIM] = hsrc[i];
    __syncthreads();

    int s = tid / VOCAB;        // 0..7
    int v = tid - s * VOCAB;    // 0..35
    float a = fc_b[v];
#pragma unroll 8
    for (int k = 0; k < H_DIM; k++) a += hs[s][k] * Ws[v][k];
    float l = fmaxf(a, 0.0f);   // relu
    lg[s][v] = l;
    __syncthreads();

    if (v == 0) {
        float m = -1e30f;
        for (int j = 0; j < VOCAB; j++) m = fmaxf(m, lg[s][j]);
        float sum = 0.0f;
        for (int j = 0; j < VOCAB; j++) sum += expf(lg[s][j] - m);
        lse_s[s] = m + logf(sum);
    }
    __syncthreads();

    float lse = lse_s[s];
    int n = n0 + s;
    out[((size_t)n * T_STEPS + t) * VOCAB + v] = expf(l - lse);   // probs
    int tgt = x[n * SEQ_S + t + 1];
    if (v == tgt && tgt != 0) atomicAdd(&g_acc[n], lse - l);      // masked NLL
}

// ---------------- finalize: molecule_loss + mean loss ----------------
__global__ void finalize_kernel(float* __restrict__ out) {
    __shared__ float red[1024];
    int tid = threadIdx.x;
    float sum = 0.0f;
    for (int n = tid; n < N_SEQ; n += 1024) {
        float ml = g_acc[n] / g_len[n];
        out[PROBS_OFF + n] = ml;
        sum += ml;
    }
    red[tid] = sum;
    __syncthreads();
    for (int sft = 512; sft > 0; sft >>= 1) {
        if (tid < sft) red[tid] += red[tid + sft];
        __syncthreads();
    }
    if (tid == 0) out[PROBS_OFF + N_SEQ] = red[0] / (float)N_SEQ;
}

// ---------------- launch ----------------
extern "C" void kernel_launch(void* const* d_in, const int* in_sizes, int n_in,
                              void* d_out, int out_size) {
    const int*   x     = (const int*)  d_in[0];
    const float* emb   = (const float*)d_in[1];
    const float* W_ih0 = (const float*)d_in[2];
    const float* W_hh0 = (const float*)d_in[3];
    const float* b_ih0 = (const float*)d_in[4];
    const float* b_hh0 = (const float*)d_in[5];
    const float* W_ih1 = (const float*)d_in[6];
    const float* W_hh1 = (const float*)d_in[7];
    const float* b_ih1 = (const float*)d_in[8];
    const float* b_hh1 = (const float*)d_in[9];
    const float* fc_W  = (const float*)d_in[10];
    const float* fc_b  = (const float*)d_in[11];
    float* out = (float*)d_out;

    prep_kernel<<<G_DIM, 128>>>(W_ih0, W_hh0, b_ih0, b_hh0, W_ih1, W_hh1, b_ih1, b_hh1);
    init_kernel<<<NH / 256, 256>>>();
    len_kernel<<<N_SEQ / 8, 256>>>(x);

    dim3 grid(G_DIM / 64, N_SEQ / 128);   // 16 x 32 = 512 blocks
    for (int t = 0; t < T_STEPS; t++) {
        lstm_step_kernel<E_DIM><<<grid, 256>>>(emb, x, t);
        lstm_step_kernel<H_DIM><<<grid, 256>>>(emb, x, t);
    }

    fc_kernel<<<dim3(N_SEQ / 8, T_STEPS), 288>>>(fc_W, fc_b, x, out);
    finalize_kernel<<<1, 1024>>>(out);
}

// round 2
// speedup vs baseline: 1.0041x; 1.0041x over previous
#include <cuda_runtime.h>
#include <math.h>

#define N_SEQ 4096
#define SEQ_S 128
#define T_STEPS 127
#define VOCAB 36
#define E_DIM 128
#define H_DIM 256
#define G_DIM 1024            // 4*H
#define NH (N_SEQ * H_DIM)    // 1048576

static const size_t PROBS_OFF = (size_t)N_SEQ * T_STEPS * VOCAB;  // 18726912

// ---------------- scratch (device globals; no allocation allowed) ----------------
__device__ __align__(128) float g_h0[2][NH];                       // layer0 h ping-pong
__device__ __align__(128) float g_hz[NH];                          // zero h for t=0
__device__ __align__(128) float g_c0[NH];
__device__ __align__(128) float g_c1[NH];
__device__ __align__(128) float g_h1all[(size_t)T_STEPS * NH];     // layer1 h, all steps (533MB)
__device__ __align__(128) float g_Wcat0[G_DIM * 384];              // [W_ih0 | W_hh0], gate-permuted rows
__device__ __align__(128) float g_Wcat1[G_DIM * 512];              // [W_ih1 | W_hh1], gate-permuted rows
__device__ float g_bcat0[G_DIM];
__device__ float g_bcat1[G_DIM];
__device__ float g_acc[N_SEQ];                                     // masked NLL accumulator
__device__ float g_len[N_SEQ];

// ---------------- helpers ----------------
typedef unsigned long long ull;

__device__ __forceinline__ ull pack2(float x, float y) {
    ull r; asm("mov.b64 %0, {%1,%2};" : "=l"(r) : "f"(x), "f"(y)); return r;
}
__device__ __forceinline__ void unpack2(ull v, float& x, float& y) {
    asm("mov.b64 {%0,%1}, %2;" : "=f"(x), "=f"(y) : "l"(v));
}
// sm_103a packed fp32 FMA: d = a*b + d (per 32-bit lane)
__device__ __forceinline__ void ffma2(ull& d, ull a, ull b) {
    asm("fma.rn.f32x2 %0, %1, %2, %0;" : "+l"(d) : "l"(a), "l"(b));
}
__device__ __forceinline__ float sigmf(float v) { return 1.0f / (1.0f + expf(-v)); }

// ---------------- prep: permute gate rows into (i,f,g,o) quadruples, concat W_ih|W_hh ----------------
__global__ void prep_kernel(const float* __restrict__ W_ih0, const float* __restrict__ W_hh0,
                            const float* __restrict__ b_ih0, const float* __restrict__ b_hh0,
                            const float* __restrict__ W_ih1, const float* __restrict__ W_hh1,
                            const float* __restrict__ b_ih1, const float* __restrict__ b_hh1) {
    int jp = blockIdx.x;                 // permuted row 0..1023
    int gate = jp & 3, q = jp >> 2;
    int j = gate * H_DIM + q;            // original row
    int tid = threadIdx.x;               // 128 threads
    for (int k = tid; k < E_DIM; k += 128) g_Wcat0[jp * 384 + k] = W_ih0[j * E_DIM + k];
    for (int k = tid; k < H_DIM; k += 128) g_Wcat0[jp * 384 + E_DIM + k] = W_hh0[j * H_DIM + k];
    for (int k = tid; k < H_DIM; k += 128) g_Wcat1[jp * 512 + k] = W_ih1[j * H_DIM + k];
    for (int k = tid; k < H_DIM; k += 128) g_Wcat1[jp * 512 + H_DIM + k] = W_hh1[j * H_DIM + k];
    if (tid == 0) {
        g_bcat0[jp] = b_ih0[j] + b_hh0[j];
        g_bcat1[jp] = b_ih1[j] + b_hh1[j];
    }
}

// ---------------- init: zero state (re-done every launch; must be deterministic) ----------------
__global__ void init_kernel() {
    int i = blockIdx.x * blockDim.x + threadIdx.x;   // exactly NH threads
    g_hz[i] = 0.0f;
    g_c0[i] = 0.0f;
    g_c1[i] = 0.0f;
    if (i < N_SEQ) g_acc[i] = 0.0f;
}

// ---------------- lengths ----------------
__global__ void len_kernel(const int* __restrict__ x) {
    int n = blockIdx.x * 8 + (threadIdx.x >> 5);
    int lane = threadIdx.x & 31;
    int cnt = 0;
    for (int j = lane; j < SEQ_S; j += 32) cnt += (x[n * SEQ_S + j] != 0);
    for (int o = 16; o; o >>= 1) cnt += __shfl_down_sync(0xffffffffu, cnt, o);
    if (lane == 0) g_len[n] = (float)cnt;
}

// ---------------- fused LSTM step: gates GEMM (fp32x2 FFMA) + pointwise update ----------------
// Block tile: 128 sequences x 64 permuted gate cols (16 complete quadruples), K = KIN + 256.
// Thread (tx,ty): rows rowBase + ty*8 + {0..7}, cols colBase + tx*4 + {0..3} (one quadruple).
template <int KIN>
__global__ __launch_bounds__(256)
void lstm_step_kernel(const float* __restrict__ emb, const int* __restrict__ x, int t) {
    constexpr int KTOT = KIN + H_DIM;
    constexpr int NT = KTOT / 16;
    __shared__ float As[16][132];
    __shared__ float Bs[16][68];
    __shared__ int tokS[128];

    const float* inp; const float* hprev; float* hnew; float* cst;
    const float* Wc; const float* bc;
    if (KIN == E_DIM) {  // layer 0: input = embedding gather
        inp = emb;
        hprev = (t == 0) ? g_hz : g_h0[(t - 1) & 1];
        hnew = g_h0[t & 1];
        cst = g_c0; Wc = g_Wcat0; bc = g_bcat0;
    } else {             // layer 1: input = layer0 output of this step
        inp = g_h0[t & 1];
        hprev = (t == 0) ? g_hz : (g_h1all + (size_t)(t - 1) * NH);
        hnew = g_h1all + (size_t)t * NH;
        cst = g_c1; Wc = g_Wcat1; bc = g_bcat1;
    }

    const int rowBase = blockIdx.y * 128;
    const int colBase = blockIdx.x * 64;
    const int tid = threadIdx.x;
    const int tx = tid & 15, ty = tid >> 4;

    if (tid < 128)
        tokS[tid] = (KIN == E_DIM) ? x[(rowBase + tid) * SEQ_S + t] : (rowBase + tid);
    __syncthreads();

    float4 aR0, aR1, bR;

    auto loadA = [&](int kt, int s) -> float4 {
        int row = s >> 2, k4 = s & 3;
        int gk = kt * 16 + k4 * 4;
        const float* p = (gk < KIN)
            ? (inp + (size_t)tokS[row] * KIN + gk)
            : (hprev + (size_t)(rowBase + row) * H_DIM + (gk - KIN));
        return *(const float4*)p;
    };
    auto loadB = [&](int kt) -> float4 {
        int c = tid >> 2, k4 = tid & 3;
        return *(const float4*)(Wc + (size_t)(colBase + c) * KTOT + kt * 16 + k4 * 4);
    };
    auto storeT = [&]() {
        int r0 = tid >> 2, k4 = tid & 3;
        As[k4 * 4 + 0][r0] = aR0.x; As[k4 * 4 + 1][r0] = aR0.y;
        As[k4 * 4 + 2][r0] = aR0.z; As[k4 * 4 + 3][r0] = aR0.w;
        int r1 = r0 + 64;
        As[k4 * 4 + 0][r1] = aR1.x; As[k4 * 4 + 1][r1] = aR1.y;
        As[k4 * 4 + 2][r1] = aR1.z; As[k4 * 4 + 3][r1] = aR1.w;
        int c = tid >> 2;
        Bs[k4 * 4 + 0][c] = bR.x; Bs[k4 * 4 + 1][c] = bR.y;
        Bs[k4 * 4 + 2][c] = bR.z; Bs[k4 * 4 + 3][c] = bR.w;
    };

    ull acc[4][4];
#pragma unroll
    for (int u = 0; u < 4; u++)
#pragma unroll
        for (int j = 0; j < 4; j++) acc[u][j] = pack2(0.0f, 0.0f);

    aR0 = loadA(0, tid); aR1 = loadA(0, tid + 256); bR = loadB(0);
    storeT();
    __syncthreads();

    for (int kt = 0; kt < NT; kt++) {
        if (kt + 1 < NT) {
            aR0 = loadA(kt + 1, tid); aR1 = loadA(kt + 1, tid + 256); bR = loadB(kt + 1);
        }
#pragma unroll
        for (int k = 0; k < 16; k++) {
            ull ap0 = *(const ull*)&As[k][ty * 8 + 0];
            ull ap1 = *(const ull*)&As[k][ty * 8 + 2];
            ull ap2 = *(const ull*)&As[k][ty * 8 + 4];
            ull ap3 = *(const ull*)&As[k][ty * 8 + 6];
            float4 b4 = *(const float4*)&Bs[k][tx * 4];
            ull bp0 = pack2(b4.x, b4.x), bp1 = pack2(b4.y, b4.y);
            ull bp2 = pack2(b4.z, b4.z), bp3 = pack2(b4.w, b4.w);
            ffma2(acc[0][0], ap0, bp0); ffma2(acc[0][1], ap0, bp1);
            ffma2(acc[0][2], ap0, bp2); ffma2(acc[0][3], ap0, bp3);
            ffma2(acc[1][0], ap1, bp0); ffma2(acc[1][1], ap1, bp1);
            ffma2(acc[1][2], ap1, bp2); ffma2(acc[1][3], ap1, bp3);
            ffma2(acc[2][0], ap2, bp0); ffma2(acc[2][1], ap2, bp1);
            ffma2(acc[2][2], ap2, bp2); ffma2(acc[2][3], ap2, bp3);
            ffma2(acc[3][0], ap3, bp0); ffma2(acc[3][1], ap3, bp1);
            ffma2(acc[3][2], ap3, bp2); ffma2(acc[3][3], ap3, bp3);
        }
        __syncthreads();
        if (kt + 1 < NT) { storeT(); __syncthreads(); }
    }

    // pointwise LSTM update (this thread owns quadruple q for its 8 rows)
    float bi = bc[colBase + tx * 4 + 0];
    float bf = bc[colBase + tx * 4 + 1];
    float bg = bc[colBase + tx * 4 + 2];
    float bo = bc[colBase + tx * 4 + 3];
    int q = (colBase >> 2) + tx;
#pragma unroll
    for (int u = 0; u < 4; u++) {
        float gi0, gi1, gf0, gf1, gg0, gg1, go0, go1;
        unpack2(acc[u][0], gi0, gi1);
        unpack2(acc[u][1], gf0, gf1);
        unpack2(acc[u][2], gg0, gg1);
        unpack2(acc[u][3], go0, go1);
        int r = rowBase + ty * 8 + 2 * u;
        {
            size_t ci = (size_t)r * H_DIM + q;
            float ii = sigmf(gi0 + bi), ff = sigmf(gf0 + bf);
            float gg = tanhf(gg0 + bg), oo = sigmf(go0 + bo);
            float cn = ff * cst[ci] + ii * gg;
            cst[ci] = cn;
            hnew[ci] = oo * tanhf(cn);
        }
        {
            size_t ci = (size_t)(r + 1) * H_DIM + q;
            float ii = sigmf(gi1 + bi), ff = sigmf(gf1 + bf);
            float gg = tanhf(gg1 + bg), oo = sigmf(go1 + bo);
            float cn = ff * cst[ci] + ii * gg;
            cst[ci] = cn;
            hnew[ci] = oo * tanhf(cn);
        }
    }
}

// ---------------- fc + relu + log_softmax + probs + masked NLL, for all (n,t) ----------------
// Block: 8 sequences x 36 vocab = 288 threads; grid (N/8, T)
__global__ __launch_bounds__(288)
void fc_kernel(const float* __restrict__ fc_W, const float* __restrict__ fc_b,
               const int* __restrict__ x, float* __restrict__ out) {
    __shared__ float Ws[VOCAB][H_DIM + 1];   // 36*257*4 = 37KB
    __shared__ float hs[8][H_DIM];           // 8KB
    __shared__ float lg[8][VOCAB + 2];
    __shared__ float lse_s[8];

    const int t = blockIdx.y;
    const int n0 = blockIdx.x * 8;
    const int tid = threadIdx.x;

    for (int i = tid; i < VOCAB * H_DIM; i += 288) Ws[i / H_DIM][i % H_DIM] = fc_W[i];
    const float* hsrc = g_h1all + (size_t)t * NH + (size_t)n0 * H_DIM;
    for (int i = tid; i < 8 * H_DIM; i += 288) hs[i / H_DIM][i % H_DIM] = hsrc[i];
    __syncthreads();

    int s = tid / VOCAB;        // 0..7
    int v = tid - s * VOCAB;    // 0..35
    float a = fc_b[v];
#pragma unroll 8
    for (int k = 0; k < H_DIM; k++) a += hs[s][k] * Ws[v][k];
    float l = fmaxf(a, 0.0f);   // relu
    lg[s][v] = l;
    __syncthreads();

    if (v == 0) {
        float m = -1e30f;
        for (int j = 0; j < VOCAB; j++) m = fmaxf(m, lg[s][j]);
        float sum = 0.0f;
        for (int j = 0; j < VOCAB; j++) sum += expf(lg[s][j] - m);
        lse_s[s] = m + logf(sum);
    }
    __syncthreads();

    float lse = lse_s[s];
    int n = n0 + s;
    out[((size_t)n * T_STEPS + t) * VOCAB + v] = expf(l - lse);   // probs
    int tgt = x[n * SEQ_S + t + 1];
    if (v == tgt && tgt != 0) atomicAdd(&g_acc[n], lse - l);      // masked NLL
}

// ---------------- finalize: molecule_loss + mean loss ----------------
__global__ void finalize_kernel(float* __restrict__ out) {
    __shared__ float red[1024];
    int tid = threadIdx.x;
    float sum = 0.0f;
    for (int n = tid; n < N_SEQ; n += 1024) {
        float ml = g_acc[n] / g_len[n];
        out[PROBS_OFF + n] = ml;
        sum += ml;
    }
    red[tid] = sum;
    __syncthreads();
    for (int sft = 512; sft > 0; sft >>= 1) {
        if (tid < sft) red[tid] += red[tid + sft];
        __syncthreads();
    }
    if (tid == 0) out[PROBS_OFF + N_SEQ] = red[0] / (float)N_SEQ;
}

// ---------------- launch ----------------
extern "C" void kernel_launch(void* const* d_in, const int* in_sizes, int n_in,
                              void* d_out, int out_size) {
    const int*   x     = (const int*)  d_in[0];
    const float* emb   = (const float*)d_in[1];
    const float* W_ih0 = (const float*)d_in[2];
    const float* W_hh0 = (const float*)d_in[3];
    const float* b_ih0 = (const float*)d_in[4];
    const float* b_hh0 = (const float*)d_in[5];
    const float* W_ih1 = (const float*)d_in[6];
    const float* W_hh1 = (const float*)d_in[7];
    const float* b_ih1 = (const float*)d_in[8];
    const float* b_hh1 = (const float*)d_in[9];
    const float* fc_W  = (const float*)d_in[10];
    const float* fc_b  = (const float*)d_in[11];
    float* out = (float*)d_out;

    prep_kernel<<<G_DIM, 128>>>(W_ih0, W_hh0, b_ih0, b_hh0, W_ih1, W_hh1, b_ih1, b_hh1);
    init_kernel<<<NH / 256, 256>>>();
    len_kernel<<<N_SEQ / 8, 256>>>(x);

    dim3 grid(G_DIM / 64, N_SEQ / 128);   // 16 x 32 = 512 blocks
    for (int t = 0; t < T_STEPS; t++) {
        lstm_step_kernel<E_DIM><<<grid, 256>>>(emb, x, t);
        lstm_step_kernel<H_DIM><<<grid, 256>>>(emb, x, t);
    }

    fc_kernel<<<dim3(N_SEQ / 8, T_STEPS), 288>>>(fc_W, fc_b, x, out);
    finalize_kernel<<<1, 1024>>>(out);
}